// round 8
// baseline (speedup 1.0000x reference)
#include <cuda_runtime.h>
#include <cuda_fp16.h>
#include <mma.h>
#include <math.h>
#include <stdint.h>

using namespace nvcuda;

// Problem dims
#define L_   4
#define D_   1024
#define DK_  64
#define B_   8
#define S_   512
#define FF_  4096
#define BS_  (B_ * S_)           // 4096 rows
#define NQKV 256                 // qkv buffer pitch (192 used: q|k|v)
#define NQ_  192                 // computed qkv columns
#define EPS_ 1e-3f

// -------------------- scratch (device globals; no allocations) ---------------
__device__ float  g_x[BS_ * D_];             // activations fp32 (residual source)
__device__ __half g_xh[BS_ * D_];            // activations half (GEMM A)
__device__ __half g_qkvh[BS_ * NQKV];        // q|k|v half (pitch 256)
__device__ __half g_sch[B_ * S_ * S_];       // scores half
__device__ __half g_ph[B_ * S_ * S_];        // probs half
__device__ __half g_hh[BS_ * DK_];           // head out half
__device__ __half g_fh[BS_ * FF_];           // ffn hidden half
__device__ __half g_w1t[L_ * FF_ * D_];      // w1^T half
__device__ __half g_w2t[L_ * D_ * FF_];      // w2^T half
__device__ __half g_wot[L_ * D_ * DK_];      // wo^T half
__device__ __half g_wqkvt[L_ * NQKV * D_];   // packed qkv^T half
__device__ float  g_bqkv[L_ * NQKV];

__device__ __forceinline__ uint32_t smem_u32(const void* p) {
    uint32_t a;
    asm("{ .reg .u64 t; cvta.to.shared.u64 t, %1; cvt.u32.u64 %0, t; }" : "=r"(a) : "l"(p));
    return a;
}

// ======================= wmma FP16 pipelined GEMM ============================
// C[M, N] = A[M, K(ldA)] @ B   (A, B half)
// BRM==0: B is Bt [N, K] K-major (ldB)   BRM==1: B is [K, N] row-major (ldB)
// CTA tile BM x BN, K chunk 64, 3-stage cp.async pipeline, 8 warps (4m x 2n),
// warp tile (BM/4) x (BN/2), wmma m16n16k16 fp16 -> fp32 accum.
// Outputs: Cf (fp32, optional) and Ch (half, optional), pitch ldC.
// mode 0: +bias   1: +bias, relu   2: BN(res + bias + acc)   3: acc * 0.125
#define STAGES 3

template<int BM, int BN, int BRM>
__global__ void __launch_bounds__(256, (BM >= 256 ? 1 : 2)) wgemm(
    const __half* __restrict__ A, int ldA,
    const __half* __restrict__ B, int ldB,
    const float* __restrict__ bias,
    float* __restrict__ Cf, __half* __restrict__ Ch,
    int N, int ldC, int K, long sA, long sB, long sC,
    int mode,
    const float* __restrict__ res,
    const float* __restrict__ gamma, const float* __restrict__ beta,
    const float* __restrict__ mean,  const float* __restrict__ var)
{
    constexpr int BK = 64;
    constexpr int LDSA = BK + 8;                        // 72 halves (144B)
    constexpr int LDSB = BRM ? (BN + 8) : (BK + 8);
    constexpr int A_STG = BM * LDSA;                    // halves
    constexpr int B_STG = BRM ? (BK * LDSB) : (BN * LDSB);
    constexpr int STG = A_STG + B_STG;
    constexpr int WM = BM / 4;                          // warp m extent
    constexpr int WN = BN / 2;                          // warp n extent
    constexpr int MT = WM / 16;
    constexpr int NT = WN / 16;

    extern __shared__ char smraw[];
    __half* sm = (__half*)smraw;

    const int tid = threadIdx.x;
    const int wid = tid >> 5;
    const int warp_m = wid & 3;
    const int warp_n = wid >> 2;
    const int m0 = blockIdx.y * BM;
    const int n0 = blockIdx.x * BN;
    const int bz = blockIdx.z;
    A += bz * sA; B += bz * sB;
    if (Cf)  Cf += bz * sC;
    if (Ch)  Ch += bz * sC;
    if (res) res += bz * sC;

    const int NK = K >> 6;

    auto load_chunk = [&](int chunk, int stage) {
        __half* smA = sm + stage * STG;
        __half* smB = smA + A_STG;
        const __half* gA = A + (long)m0 * ldA + chunk * 64;
        #pragma unroll
        for (int j = 0; j < BM / 32; j++) {             // A: BM rows x 8 x 16B
            int idx = tid + j * 256;
            int r = idx >> 3, c8 = (idx & 7) * 8;
            uint32_t dst = smem_u32(&smA[r * LDSA + c8]);
            const __half* src = gA + (long)r * ldA + c8;
            asm volatile("cp.async.cg.shared.global [%0], [%1], 16;" :: "r"(dst), "l"(src));
        }
        if (BRM) {
            const __half* gB = B + (long)(chunk * 64) * ldB + n0;
            constexpr int CPR = BN / 8;
            #pragma unroll
            for (int j = 0; j < BN / 32; j++) {         // 64 rows x CPR x 16B
                int idx = tid + j * 256;
                int r = idx / CPR, c8 = (idx % CPR) * 8;
                uint32_t dst = smem_u32(&smB[r * LDSB + c8]);
                const __half* src = gB + (long)r * ldB + c8;
                asm volatile("cp.async.cg.shared.global [%0], [%1], 16;" :: "r"(dst), "l"(src));
            }
        } else {
            const __half* gB = B + (long)n0 * ldB + chunk * 64;
            #pragma unroll
            for (int j = 0; j < BN / 32; j++) {         // BN rows x 8 x 16B
                int idx = tid + j * 256;
                int r = idx >> 3, c8 = (idx & 7) * 8;
                uint32_t dst = smem_u32(&smB[r * LDSB + c8]);
                const __half* src = gB + (long)r * ldB + c8;
                asm volatile("cp.async.cg.shared.global [%0], [%1], 16;" :: "r"(dst), "l"(src));
            }
        }
        asm volatile("cp.async.commit_group;" ::: "memory");
    };

    wmma::fragment<wmma::accumulator, 16, 16, 16, float> acc[MT][NT];
    #pragma unroll
    for (int i = 0; i < MT; i++)
        #pragma unroll
        for (int j = 0; j < NT; j++) wmma::fill_fragment(acc[i][j], 0.f);

    load_chunk(0, 0);
    if (NK > 1) load_chunk(1, 1);

    for (int i = 0; i < NK; i++) {
        if (i < NK - 1) asm volatile("cp.async.wait_group 1;" ::: "memory");
        else            asm volatile("cp.async.wait_group 0;" ::: "memory");
        __syncthreads();

        if (i + 2 < NK) load_chunk(i + 2, (i + 2) % STAGES);

        const __half* sA = sm + (i % STAGES) * STG;
        const __half* sB = sA + A_STG;

        #pragma unroll
        for (int ks = 0; ks < 4; ks++) {
            int kk = ks * 16;
            wmma::fragment<wmma::matrix_a, 16, 16, 16, __half, wmma::row_major> af[MT];
            #pragma unroll
            for (int mi = 0; mi < MT; mi++)
                wmma::load_matrix_sync(af[mi], sA + (warp_m * WM + mi * 16) * LDSA + kk, LDSA);
            if (BRM) {
                wmma::fragment<wmma::matrix_b, 16, 16, 16, __half, wmma::row_major> bf[NT];
                #pragma unroll
                for (int nj = 0; nj < NT; nj++)
                    wmma::load_matrix_sync(bf[nj], sB + kk * LDSB + warp_n * WN + nj * 16, LDSB);
                #pragma unroll
                for (int mi = 0; mi < MT; mi++)
                    #pragma unroll
                    for (int nj = 0; nj < NT; nj++)
                        wmma::mma_sync(acc[mi][nj], af[mi], bf[nj], acc[mi][nj]);
            } else {
                wmma::fragment<wmma::matrix_b, 16, 16, 16, __half, wmma::col_major> bf[NT];
                #pragma unroll
                for (int nj = 0; nj < NT; nj++)
                    wmma::load_matrix_sync(bf[nj], sB + (warp_n * WN + nj * 16) * LDSB + kk, LDSB);
                #pragma unroll
                for (int mi = 0; mi < MT; mi++)
                    #pragma unroll
                    for (int nj = 0; nj < NT; nj++)
                        wmma::mma_sync(acc[mi][nj], af[mi], bf[nj], acc[mi][nj]);
            }
        }
    }
    __syncthreads();

    // ---------------- epilogue: fp32 staging in smem, fused ops --------------
    float* stg = (float*)smraw;
    #pragma unroll
    for (int mi = 0; mi < MT; mi++)
        #pragma unroll
        for (int nj = 0; nj < NT; nj++)
            wmma::store_matrix_sync(
                stg + (long)(warp_m * WM + mi * 16) * BN + warp_n * WN + nj * 16,
                acc[mi][nj], BN, wmma::mem_row_major);
    __syncthreads();

    #pragma unroll
    for (int it = 0; it < BM * BN / 4 / 256; it++) {
        int idx = (tid + it * 256) * 4;
        int r = idx / BN, c = idx % BN;
        int gc = n0 + c;
        float4 o = *(const float4*)&stg[idx];
        if (bias) {
            float4 bb = *(const float4*)&bias[gc];
            o.x += bb.x; o.y += bb.y; o.z += bb.z; o.w += bb.w;
        }
        if (mode == 1) {
            o.x = fmaxf(o.x, 0.f); o.y = fmaxf(o.y, 0.f);
            o.z = fmaxf(o.z, 0.f); o.w = fmaxf(o.w, 0.f);
        } else if (mode == 2) {
            float4 rr = *(const float4*)&res[(long)(m0 + r) * ldC + gc];
            float4 gg = *(const float4*)&gamma[gc];
            float4 be = *(const float4*)&beta[gc];
            float4 mm = *(const float4*)&mean[gc];
            float4 va = *(const float4*)&var[gc];
            o.x = gg.x * (o.x + rr.x - mm.x) * rsqrtf(va.x + EPS_) + be.x;
            o.y = gg.y * (o.y + rr.y - mm.y) * rsqrtf(va.y + EPS_) + be.y;
            o.z = gg.z * (o.z + rr.z - mm.z) * rsqrtf(va.z + EPS_) + be.z;
            o.w = gg.w * (o.w + rr.w - mm.w) * rsqrtf(va.w + EPS_) + be.w;
        } else if (mode == 3) {
            o.x *= 0.125f; o.y *= 0.125f; o.z *= 0.125f; o.w *= 0.125f;
        }
        long off = (long)(m0 + r) * ldC + gc;
        if (Cf) *(float4*)&Cf[off] = o;
        if (Ch) {
            __half2 h0 = __floats2half2_rn(o.x, o.y);
            __half2 h1 = __floats2half2_rn(o.z, o.w);
            *(uint2*)&Ch[off] = make_uint2(*(uint32_t*)&h0, *(uint32_t*)&h1);
        }
    }
}

// ======================= small prep / misc kernels ===========================
__global__ void __launch_bounds__(256) embed_kernel(
    const int* __restrict__ seq, const float* __restrict__ emb,
    const float* __restrict__ pes, float* __restrict__ x, __half* __restrict__ xh)
{
    int bs = blockIdx.x;
    int s  = bs & (S_ - 1);
    int tok = seq[bs];
    float p = pes[(long)s * D_];
    const float4* e = (const float4*)(emb + (long)tok * D_);
    float4 v = e[threadIdx.x];
    v.x += p; v.y += p; v.z += p; v.w += p;
    ((float4*)(x + (long)bs * D_))[threadIdx.x] = v;
    __half2 h0 = __floats2half2_rn(v.x, v.y);
    __half2 h1 = __floats2half2_rn(v.z, v.w);
    ((uint2*)(xh + (long)bs * D_))[threadIdx.x] = make_uint2(*(uint32_t*)&h0, *(uint32_t*)&h1);
}

// fp32 -> half transpose: out[c][r] = in[r][c]; batched by blockIdx.z
__global__ void __launch_bounds__(256) transpose_f2h(
    const float* __restrict__ in, __half* __restrict__ out,
    int R, int C, int ldIn, long sIn, long sOut)
{
    __shared__ float t[32][33];
    in += (long)blockIdx.z * sIn; out += (long)blockIdx.z * sOut;
    int c0 = blockIdx.x * 32, r0 = blockIdx.y * 32;
    int tx = threadIdx.x, ty = threadIdx.y;
    #pragma unroll
    for (int j = 0; j < 32; j += 8)
        t[ty + j][tx] = in[(long)(r0 + ty + j) * ldIn + c0 + tx];
    __syncthreads();
    #pragma unroll
    for (int j = 0; j < 32; j += 8)
        out[(long)(c0 + ty + j) * R + r0 + tx] = __float2half_rn(t[tx][ty + j]);
}

// pack wq|wk|wv -> half wqkvt [L][256][1024] (transposed) + fp32 bias pack
__global__ void __launch_bounds__(256) qkvpack(
    const float* __restrict__ wq, const float* __restrict__ wk,
    const float* __restrict__ wv, const float* __restrict__ bq,
    const float* __restrict__ bk, const float* __restrict__ bv,
    __half* __restrict__ wt, float* __restrict__ bt)
{
    int l = blockIdx.z;
    int n = blockIdx.y;                         // 0..255
    int k = blockIdx.x * 256 + threadIdx.x;     // 0..1023
    const float* src = (n < 64) ? wq : (n < 128) ? wk : (n < 192) ? wv : nullptr;
    int j = n & 63;
    float v = 0.f;
    if (src) v = src[((long)l * D_ + k) * DK_ + j];
    wt[((long)l * NQKV + n) * D_ + k] = __float2half_rn(v);
    if (blockIdx.x == 0 && threadIdx.x == 0) {
        const float* bs = (n < 64) ? bq : (n < 128) ? bk : (n < 192) ? bv : nullptr;
        bt[l * NQKV + n] = bs ? bs[l * DK_ + j] : 0.f;
    }
}

// softmax over 512 half scores -> half probs (fp32 math inside)
__global__ void __launch_bounds__(256) softmax512(
    const __half* __restrict__ sc, __half* __restrict__ ph)
{
    __shared__ float red[256];
    const __half* r = sc + (long)blockIdx.x * S_;
    __half* o = ph + (long)blockIdx.x * S_;
    int t = threadIdx.x;
    float a = __half2float(r[t]), b = __half2float(r[t + 256]);
    red[t] = fmaxf(a, b);
    __syncthreads();
    for (int s = 128; s > 0; s >>= 1) {
        if (t < s) red[t] = fmaxf(red[t], red[t + s]);
        __syncthreads();
    }
    float m = red[0];
    __syncthreads();
    float ea = __expf(a - m), eb = __expf(b - m);
    red[t] = ea + eb;
    __syncthreads();
    for (int s = 128; s > 0; s >>= 1) {
        if (t < s) red[t] += red[t + s];
        __syncthreads();
    }
    float inv = 1.0f / red[0];
    o[t] = __float2half_rn(ea * inv);
    o[t + 256] = __float2half_rn(eb * inv);
}

// ------------------------------------------------------------------------------
extern "C" void kernel_launch(void* const* d_in, const int* in_sizes, int n_in,
                              void* d_out, int out_size)
{
    const int*   seq  = (const int*)  d_in[0];
    const float* emb  = (const float*)d_in[1];
    const float* pes  = (const float*)d_in[2];
    const float* wq   = (const float*)d_in[3];
    const float* bq   = (const float*)d_in[4];
    const float* wk   = (const float*)d_in[5];
    const float* bk   = (const float*)d_in[6];
    const float* wv   = (const float*)d_in[7];
    const float* bv   = (const float*)d_in[8];
    const float* wo   = (const float*)d_in[9];
    const float* bo   = (const float*)d_in[10];
    const float* agam = (const float*)d_in[11];
    const float* abet = (const float*)d_in[12];
    const float* amea = (const float*)d_in[13];
    const float* avar = (const float*)d_in[14];
    const float* w1   = (const float*)d_in[15];
    const float* bff1 = (const float*)d_in[16];
    const float* w2   = (const float*)d_in[17];
    const float* bff2 = (const float*)d_in[18];
    const float* fgam = (const float*)d_in[19];
    const float* fbet = (const float*)d_in[20];
    const float* fmea = (const float*)d_in[21];
    const float* fvar = (const float*)d_in[22];
    float* out = (float*)d_out;

    float *x, *bqkv;
    __half *xh, *qkvh, *sch, *ph, *hh, *fh, *w1t, *w2t, *wot, *wqkvt;
    cudaGetSymbolAddress((void**)&x, g_x);
    cudaGetSymbolAddress((void**)&xh, g_xh);
    cudaGetSymbolAddress((void**)&qkvh, g_qkvh);
    cudaGetSymbolAddress((void**)&sch, g_sch);
    cudaGetSymbolAddress((void**)&ph, g_ph);
    cudaGetSymbolAddress((void**)&hh, g_hh);
    cudaGetSymbolAddress((void**)&fh, g_fh);
    cudaGetSymbolAddress((void**)&w1t, g_w1t);
    cudaGetSymbolAddress((void**)&w2t, g_w2t);
    cudaGetSymbolAddress((void**)&wot, g_wot);
    cudaGetSymbolAddress((void**)&wqkvt, g_wqkvt);
    cudaGetSymbolAddress((void**)&bqkv, g_bqkv);

    // dynamic smem: 3 stages * (A + B) halves * 2B  (epilogue staging fits within)
    const int SM_12864  = 3 * (128 * 72 + 64 * 72) * 2;    // 82944
    const int SM_128128 = 3 * (128 * 72 + 128 * 72) * 2;   // 110592
    const int SM_256128 = 3 * (256 * 72 + 128 * 72) * 2;   // 165888
    cudaFuncSetAttribute((const void*)wgemm<128, 64, 0>,
                         cudaFuncAttributeMaxDynamicSharedMemorySize, SM_12864);
    cudaFuncSetAttribute((const void*)wgemm<128, 64, 1>,
                         cudaFuncAttributeMaxDynamicSharedMemorySize, SM_12864);
    cudaFuncSetAttribute((const void*)wgemm<128, 128, 0>,
                         cudaFuncAttributeMaxDynamicSharedMemorySize, SM_128128);
    cudaFuncSetAttribute((const void*)wgemm<256, 128, 0>,
                         cudaFuncAttributeMaxDynamicSharedMemorySize, SM_256128);

    dim3 tb(32, 8);
    // weight preprocessing (every replay; deterministic)
    transpose_f2h<<<dim3(FF_ / 32, D_ / 32, L_), tb>>>(w1, w1t, D_, FF_, FF_,
                                                       (long)D_ * FF_, (long)D_ * FF_);
    transpose_f2h<<<dim3(D_ / 32, FF_ / 32, L_), tb>>>(w2, w2t, FF_, D_, D_,
                                                       (long)D_ * FF_, (long)D_ * FF_);
    transpose_f2h<<<dim3(D_ / 32, DK_ / 32, L_), tb>>>(wo, wot, DK_, D_, D_,
                                                       (long)DK_ * D_, (long)DK_ * D_);
    qkvpack<<<dim3(D_ / 256, NQKV, L_), 256>>>(wq, wk, wv, bq, bk, bv, wqkvt, bqkv);

    embed_kernel<<<BS_, 256>>>(seq, emb, pes, x, xh);

    for (int l = 0; l < L_; l++) {
        const __half* w1tl = w1t + (long)l * FF_ * D_;
        const __half* w2tl = w2t + (long)l * D_ * FF_;
        const __half* wotl = wot + (long)l * D_ * DK_;
        const __half* wqkvtl = wqkvt + (long)l * NQKV * D_;
        const float* bqkvl = bqkv + l * NQKV;

        // QKV: qkvh[4096, 0:192] = xh @ wqkvt^T + bqkv   (pitch 256)
        wgemm<128, 64, 0><<<dim3(NQ_ / 64, BS_ / 128, 1), 256, SM_12864>>>(
            xh, D_, wqkvtl, D_, bqkvl, nullptr, qkvh, NQ_, NQKV, D_, 0, 0, 0,
            0, nullptr, nullptr, nullptr, nullptr, nullptr);

        // scores (half out): sch[b,512,512] = 0.125 * q @ k^T
        wgemm<128, 128, 0><<<dim3(S_ / 128, S_ / 128, B_), 256, SM_128128>>>(
            qkvh, NQKV, qkvh + 64, NQKV, nullptr, nullptr, sch, S_, S_, DK_,
            (long)S_ * NQKV, (long)S_ * NQKV, (long)S_ * S_,
            3, nullptr, nullptr, nullptr, nullptr, nullptr);

        softmax512<<<B_ * S_, 256>>>(sch, ph);

        // head: hh[b,512,64] = ph @ v   (V row-major directly from qkvh[:,128:192])
        wgemm<128, 64, 1><<<dim3(1, S_ / 128, B_), 256, SM_12864>>>(
            ph, S_, qkvh + 128, NQKV, nullptr, nullptr, hh, DK_, DK_, S_,
            (long)S_ * S_, (long)S_ * NQKV, (long)S_ * DK_,
            0, nullptr, nullptr, nullptr, nullptr, nullptr);

        // att out + residual + BN: x = BN(x + hh @ wo + bo)
        wgemm<256, 128, 0><<<dim3(D_ / 128, BS_ / 256, 1), 256, SM_256128>>>(
            hh, DK_, wotl, DK_, bo + l * D_, x, xh, D_, D_, DK_, 0, 0, 0,
            2, x, agam + l * D_, abet + l * D_, amea + l * D_, avar + l * D_);

        // FFN1: fh = relu(xh @ w1 + b1)
        wgemm<256, 128, 0><<<dim3(FF_ / 128, BS_ / 256, 1), 256, SM_256128>>>(
            xh, D_, w1tl, D_, bff1 + l * FF_, nullptr, fh, FF_, FF_, D_, 0, 0, 0,
            1, nullptr, nullptr, nullptr, nullptr, nullptr);

        // FFN2 + residual + BN
        float* dst = (l == L_ - 1) ? out : x;
        wgemm<256, 128, 0><<<dim3(D_ / 128, BS_ / 256, 1), 256, SM_256128>>>(
            fh, FF_, w2tl, FF_, bff2 + l * D_, dst, xh, D_, D_, FF_, 0, 0, 0,
            2, x, fgam + l * D_, fbet + l * D_, fmea + l * D_, fvar + l * D_);
    }
}

// round 11
// speedup vs baseline: 1.1776x; 1.1776x over previous
#include <cuda_runtime.h>
#include <cuda_fp16.h>
#include <mma.h>
#include <math.h>
#include <stdint.h>

using namespace nvcuda;

// Problem dims
#define L_   4
#define D_   1024
#define DK_  64
#define B_   8
#define S_   512
#define FF_  4096
#define BS_  (B_ * S_)           // 4096 rows
#define NQKV 256                 // qkv buffer pitch (192 used: q|k|v)
#define NQ_  192                 // computed qkv columns
#define EPS_ 1e-3f

// -------------------- scratch (device globals; no allocations) ---------------
__device__ float  g_x[BS_ * D_];             // activations fp32 (residual source)
__device__ __half g_xh[BS_ * D_];            // activations half (GEMM A)
__device__ __half g_qkvh[BS_ * NQKV];        // q|k|v half (pitch 256)
__device__ __half g_sch[B_ * S_ * S_];       // scores half
__device__ __half g_ph[B_ * S_ * S_];        // probs half
__device__ __half g_hh[BS_ * DK_];           // head out half
__device__ __half g_fh[BS_ * FF_];           // ffn hidden half
__device__ __half g_w1t[L_ * FF_ * D_];      // w1^T half
__device__ __half g_w2t[L_ * D_ * FF_];      // w2^T half
__device__ __half g_wot[L_ * D_ * DK_];      // wo^T half
__device__ __half g_wqkvt[L_ * NQKV * D_];   // packed qkv^T half
__device__ float  g_bqkv[L_ * NQKV];

__device__ __forceinline__ uint32_t smem_u32(const void* p) {
    uint32_t a;
    asm("{ .reg .u64 t; cvta.to.shared.u64 t, %1; cvt.u32.u64 %0, t; }" : "=r"(a) : "l"(p));
    return a;
}

// ======================= wmma FP16 pipelined GEMM ============================
// C[M, N] = A[M, K(ldA)] @ B   (A, B half)
// BRM==0: B is Bt [N, K] K-major (ldB)   BRM==1: B is [K, N] row-major (ldB)
// CTA tile 128 x BN, K chunk 64, 3-stage cp.async pipeline, 8 warps (4m x 2n),
// warp tile 32 x (BN/2), wmma m16n16k16 fp16 -> fp32 accum.
// Outputs: Cf (fp32, optional) and Ch (half, optional), pitch ldC.
// mode 0: +bias   1: +bias, relu   2: BN(res + bias + acc)   3: acc * 0.125
#define STAGES 3

template<int BN, int BRM>
__global__ void __launch_bounds__(256, 2) wgemm(
    const __half* __restrict__ A, int ldA,
    const __half* __restrict__ B, int ldB,
    const float* __restrict__ bias,
    float* __restrict__ Cf, __half* __restrict__ Ch,
    int N, int ldC, int K, long sA, long sB, long sC,
    int mode,
    const float* __restrict__ res,
    const float* __restrict__ gamma, const float* __restrict__ beta,
    const float* __restrict__ mean,  const float* __restrict__ var)
{
    constexpr int BM = 128, BK = 64;
    constexpr int LDSA = BK + 8;                        // 72 halves (144B)
    constexpr int LDSB = BRM ? (BN + 8) : (BK + 8);
    constexpr int A_STG = BM * LDSA;                    // halves
    constexpr int B_STG = BRM ? (BK * LDSB) : (BN * LDSB);
    constexpr int STG = A_STG + B_STG;
    constexpr int WN = BN / 2;                          // warp n extent
    constexpr int NT = WN / 16;

    extern __shared__ char smraw[];
    __half* sm = (__half*)smraw;

    const int tid = threadIdx.x;
    const int wid = tid >> 5;
    const int warp_m = wid & 3;
    const int warp_n = wid >> 2;
    const int m0 = blockIdx.y * BM;
    const int n0 = blockIdx.x * BN;
    const int bz = blockIdx.z;
    A += bz * sA; B += bz * sB;
    if (Cf)  Cf += bz * sC;
    if (Ch)  Ch += bz * sC;
    if (res) res += bz * sC;

    const int NK = K >> 6;

    auto load_chunk = [&](int chunk, int stage) {
        __half* smA = sm + stage * STG;
        __half* smB = smA + A_STG;
        const __half* gA = A + (long)m0 * ldA + chunk * 64;
        #pragma unroll
        for (int j = 0; j < 4; j++) {                   // A: 128 rows x 8 x 16B
            int idx = tid + j * 256;
            int r = idx >> 3, c8 = (idx & 7) * 8;
            uint32_t dst = smem_u32(&smA[r * LDSA + c8]);
            const __half* src = gA + (long)r * ldA + c8;
            asm volatile("cp.async.cg.shared.global [%0], [%1], 16;" :: "r"(dst), "l"(src));
        }
        if (BRM) {
            const __half* gB = B + (long)(chunk * 64) * ldB + n0;
            constexpr int CPR = BN / 8;
            #pragma unroll
            for (int j = 0; j < BN / 32; j++) {         // 64 rows x CPR x 16B
                int idx = tid + j * 256;
                int r = idx / CPR, c8 = (idx % CPR) * 8;
                uint32_t dst = smem_u32(&smB[r * LDSB + c8]);
                const __half* src = gB + (long)r * ldB + c8;
                asm volatile("cp.async.cg.shared.global [%0], [%1], 16;" :: "r"(dst), "l"(src));
            }
        } else {
            const __half* gB = B + (long)n0 * ldB + chunk * 64;
            #pragma unroll
            for (int j = 0; j < BN / 32; j++) {         // BN rows x 8 x 16B
                int idx = tid + j * 256;
                int r = idx >> 3, c8 = (idx & 7) * 8;
                uint32_t dst = smem_u32(&smB[r * LDSB + c8]);
                const __half* src = gB + (long)r * ldB + c8;
                asm volatile("cp.async.cg.shared.global [%0], [%1], 16;" :: "r"(dst), "l"(src));
            }
        }
        asm volatile("cp.async.commit_group;" ::: "memory");
    };

    wmma::fragment<wmma::accumulator, 16, 16, 16, float> acc[2][NT];
    #pragma unroll
    for (int i = 0; i < 2; i++)
        #pragma unroll
        for (int j = 0; j < NT; j++) wmma::fill_fragment(acc[i][j], 0.f);

    load_chunk(0, 0);
    if (NK > 1) load_chunk(1, 1);

    for (int i = 0; i < NK; i++) {
        if (i < NK - 1) asm volatile("cp.async.wait_group 1;" ::: "memory");
        else            asm volatile("cp.async.wait_group 0;" ::: "memory");
        __syncthreads();

        if (i + 2 < NK) load_chunk(i + 2, (i + 2) % STAGES);

        const __half* sA = sm + (i % STAGES) * STG;
        const __half* sB = sA + A_STG;

        #pragma unroll
        for (int ks = 0; ks < 4; ks++) {
            int kk = ks * 16;
            wmma::fragment<wmma::matrix_a, 16, 16, 16, __half, wmma::row_major> af[2];
            #pragma unroll
            for (int mi = 0; mi < 2; mi++)
                wmma::load_matrix_sync(af[mi], sA + (warp_m * 32 + mi * 16) * LDSA + kk, LDSA);
            if (BRM) {
                wmma::fragment<wmma::matrix_b, 16, 16, 16, __half, wmma::row_major> bf[NT];
                #pragma unroll
                for (int nj = 0; nj < NT; nj++)
                    wmma::load_matrix_sync(bf[nj], sB + kk * LDSB + warp_n * WN + nj * 16, LDSB);
                #pragma unroll
                for (int mi = 0; mi < 2; mi++)
                    #pragma unroll
                    for (int nj = 0; nj < NT; nj++)
                        wmma::mma_sync(acc[mi][nj], af[mi], bf[nj], acc[mi][nj]);
            } else {
                wmma::fragment<wmma::matrix_b, 16, 16, 16, __half, wmma::col_major> bf[NT];
                #pragma unroll
                for (int nj = 0; nj < NT; nj++)
                    wmma::load_matrix_sync(bf[nj], sB + (warp_n * WN + nj * 16) * LDSB + kk, LDSB);
                #pragma unroll
                for (int mi = 0; mi < 2; mi++)
                    #pragma unroll
                    for (int nj = 0; nj < NT; nj++)
                        wmma::mma_sync(acc[mi][nj], af[mi], bf[nj], acc[mi][nj]);
            }
        }
    }
    __syncthreads();

    // ---------------- epilogue: fp32 staging in smem, fused ops --------------
    float* stg = (float*)smraw;
    #pragma unroll
    for (int mi = 0; mi < 2; mi++)
        #pragma unroll
        for (int nj = 0; nj < NT; nj++)
            wmma::store_matrix_sync(
                stg + (long)(warp_m * 32 + mi * 16) * BN + warp_n * WN + nj * 16,
                acc[mi][nj], BN, wmma::mem_row_major);
    __syncthreads();

    #pragma unroll
    for (int it = 0; it < BM * BN / 4 / 256; it++) {
        int idx = (tid + it * 256) * 4;
        int r = idx / BN, c = idx % BN;
        int gc = n0 + c;
        float4 o = *(const float4*)&stg[idx];
        if (bias) {
            float4 bb = *(const float4*)&bias[gc];
            o.x += bb.x; o.y += bb.y; o.z += bb.z; o.w += bb.w;
        }
        if (mode == 1) {
            o.x = fmaxf(o.x, 0.f); o.y = fmaxf(o.y, 0.f);
            o.z = fmaxf(o.z, 0.f); o.w = fmaxf(o.w, 0.f);
        } else if (mode == 2) {
            float4 rr = *(const float4*)&res[(long)(m0 + r) * ldC + gc];
            float4 gg = *(const float4*)&gamma[gc];
            float4 be = *(const float4*)&beta[gc];
            float4 mm = *(const float4*)&mean[gc];
            float4 va = *(const float4*)&var[gc];
            o.x = gg.x * (o.x + rr.x - mm.x) * rsqrtf(va.x + EPS_) + be.x;
            o.y = gg.y * (o.y + rr.y - mm.y) * rsqrtf(va.y + EPS_) + be.y;
            o.z = gg.z * (o.z + rr.z - mm.z) * rsqrtf(va.z + EPS_) + be.z;
            o.w = gg.w * (o.w + rr.w - mm.w) * rsqrtf(va.w + EPS_) + be.w;
        } else if (mode == 3) {
            o.x *= 0.125f; o.y *= 0.125f; o.z *= 0.125f; o.w *= 0.125f;
        }
        long off = (long)(m0 + r) * ldC + gc;
        if (Cf) *(float4*)&Cf[off] = o;
        if (Ch) {
            __half2 h0 = __floats2half2_rn(o.x, o.y);
            __half2 h1 = __floats2half2_rn(o.z, o.w);
            *(uint2*)&Ch[off] = make_uint2(*(uint32_t*)&h0, *(uint32_t*)&h1);
        }
    }
}

// ======================= small prep / misc kernels ===========================
__global__ void __launch_bounds__(256) embed_kernel(
    const int* __restrict__ seq, const float* __restrict__ emb,
    const float* __restrict__ pes, float* __restrict__ x, __half* __restrict__ xh)
{
    int bs = blockIdx.x;
    int s  = bs & (S_ - 1);
    int tok = seq[bs];
    float p = pes[(long)s * D_];
    const float4* e = (const float4*)(emb + (long)tok * D_);
    float4 v = e[threadIdx.x];
    v.x += p; v.y += p; v.z += p; v.w += p;
    ((float4*)(x + (long)bs * D_))[threadIdx.x] = v;
    __half2 h0 = __floats2half2_rn(v.x, v.y);
    __half2 h1 = __floats2half2_rn(v.z, v.w);
    ((uint2*)(xh + (long)bs * D_))[threadIdx.x] = make_uint2(*(uint32_t*)&h0, *(uint32_t*)&h1);
}

// fp32 -> half transpose: out[c][r] = in[r][c]; batched by blockIdx.z
__global__ void __launch_bounds__(256) transpose_f2h(
    const float* __restrict__ in, __half* __restrict__ out,
    int R, int C, int ldIn, long sIn, long sOut)
{
    __shared__ float t[32][33];
    in += (long)blockIdx.z * sIn; out += (long)blockIdx.z * sOut;
    int c0 = blockIdx.x * 32, r0 = blockIdx.y * 32;
    int tx = threadIdx.x, ty = threadIdx.y;
    #pragma unroll
    for (int j = 0; j < 32; j += 8)
        t[ty + j][tx] = in[(long)(r0 + ty + j) * ldIn + c0 + tx];
    __syncthreads();
    #pragma unroll
    for (int j = 0; j < 32; j += 8)
        out[(long)(c0 + ty + j) * R + r0 + tx] = __float2half_rn(t[tx][ty + j]);
}

// pack wq|wk|wv -> half wqkvt [L][256][1024] (transposed) + fp32 bias pack
__global__ void __launch_bounds__(256) qkvpack(
    const float* __restrict__ wq, const float* __restrict__ wk,
    const float* __restrict__ wv, const float* __restrict__ bq,
    const float* __restrict__ bk, const float* __restrict__ bv,
    __half* __restrict__ wt, float* __restrict__ bt)
{
    int l = blockIdx.z;
    int n = blockIdx.y;                         // 0..255
    int k = blockIdx.x * 256 + threadIdx.x;     // 0..1023
    const float* src = (n < 64) ? wq : (n < 128) ? wk : (n < 192) ? wv : nullptr;
    int j = n & 63;
    float v = 0.f;
    if (src) v = src[((long)l * D_ + k) * DK_ + j];
    wt[((long)l * NQKV + n) * D_ + k] = __float2half_rn(v);
    if (blockIdx.x == 0 && threadIdx.x == 0) {
        const float* bs = (n < 64) ? bq : (n < 128) ? bk : (n < 192) ? bv : nullptr;
        bt[l * NQKV + n] = bs ? bs[l * DK_ + j] : 0.f;
    }
}

// warp-per-row softmax over 512 half scores -> half probs (fp32 math)
__global__ void __launch_bounds__(256) softmax_warp(
    const __half* __restrict__ sc, __half* __restrict__ ph)
{
    int row = blockIdx.x * 8 + (threadIdx.x >> 5);
    int lane = threadIdx.x & 31;
    const __half2* r = (const __half2*)(sc + (long)row * S_);
    __half2* o = (__half2*)(ph + (long)row * S_);

    float v[16];
    float m = -1e30f;
    #pragma unroll
    for (int j = 0; j < 8; j++) {
        float2 f = __half22float2(r[lane + j * 32]);
        v[2 * j] = f.x; v[2 * j + 1] = f.y;
        m = fmaxf(m, fmaxf(f.x, f.y));
    }
    #pragma unroll
    for (int s = 16; s > 0; s >>= 1) m = fmaxf(m, __shfl_xor_sync(~0u, m, s));
    float sum = 0.f;
    #pragma unroll
    for (int j = 0; j < 16; j++) { v[j] = __expf(v[j] - m); sum += v[j]; }
    #pragma unroll
    for (int s = 16; s > 0; s >>= 1) sum += __shfl_xor_sync(~0u, sum, s);
    float inv = 1.0f / sum;
    #pragma unroll
    for (int j = 0; j < 8; j++)
        o[lane + j * 32] = __floats2half2_rn(v[2 * j] * inv, v[2 * j + 1] * inv);
}

// ------------------------------------------------------------------------------
extern "C" void kernel_launch(void* const* d_in, const int* in_sizes, int n_in,
                              void* d_out, int out_size)
{
    const int*   seq  = (const int*)  d_in[0];
    const float* emb  = (const float*)d_in[1];
    const float* pes  = (const float*)d_in[2];
    const float* wq   = (const float*)d_in[3];
    const float* bq   = (const float*)d_in[4];
    const float* wk   = (const float*)d_in[5];
    const float* bk   = (const float*)d_in[6];
    const float* wv   = (const float*)d_in[7];
    const float* bv   = (const float*)d_in[8];
    const float* wo   = (const float*)d_in[9];
    const float* bo   = (const float*)d_in[10];
    const float* agam = (const float*)d_in[11];
    const float* abet = (const float*)d_in[12];
    const float* amea = (const float*)d_in[13];
    const float* avar = (const float*)d_in[14];
    const float* w1   = (const float*)d_in[15];
    const float* bff1 = (const float*)d_in[16];
    const float* w2   = (const float*)d_in[17];
    const float* bff2 = (const float*)d_in[18];
    const float* fgam = (const float*)d_in[19];
    const float* fbet = (const float*)d_in[20];
    const float* fmea = (const float*)d_in[21];
    const float* fvar = (const float*)d_in[22];
    float* out = (float*)d_out;

    float *x, *bqkv;
    __half *xh, *qkvh, *sch, *ph, *hh, *fh, *w1t, *w2t, *wot, *wqkvt;
    cudaGetSymbolAddress((void**)&x, g_x);
    cudaGetSymbolAddress((void**)&xh, g_xh);
    cudaGetSymbolAddress((void**)&qkvh, g_qkvh);
    cudaGetSymbolAddress((void**)&sch, g_sch);
    cudaGetSymbolAddress((void**)&ph, g_ph);
    cudaGetSymbolAddress((void**)&hh, g_hh);
    cudaGetSymbolAddress((void**)&fh, g_fh);
    cudaGetSymbolAddress((void**)&w1t, g_w1t);
    cudaGetSymbolAddress((void**)&w2t, g_w2t);
    cudaGetSymbolAddress((void**)&wot, g_wot);
    cudaGetSymbolAddress((void**)&wqkvt, g_wqkvt);
    cudaGetSymbolAddress((void**)&bqkv, g_bqkv);

    // dynamic smem: 3 stages * (A + B) halves * 2B  (epilogue staging fits within)
    const int SM_64  = 3 * (128 * 72 + 64 * 72) * 2;    // 82944
    const int SM_128 = 3 * (128 * 72 + 128 * 72) * 2;   // 110592
    cudaFuncSetAttribute((const void*)wgemm<64, 0>,
                         cudaFuncAttributeMaxDynamicSharedMemorySize, SM_64);
    cudaFuncSetAttribute((const void*)wgemm<64, 1>,
                         cudaFuncAttributeMaxDynamicSharedMemorySize, SM_64);
    cudaFuncSetAttribute((const void*)wgemm<128, 0>,
                         cudaFuncAttributeMaxDynamicSharedMemorySize, SM_128);

    dim3 tb(32, 8);
    // weight preprocessing (every replay; deterministic)
    transpose_f2h<<<dim3(FF_ / 32, D_ / 32, L_), tb>>>(w1, w1t, D_, FF_, FF_,
                                                       (long)D_ * FF_, (long)D_ * FF_);
    transpose_f2h<<<dim3(D_ / 32, FF_ / 32, L_), tb>>>(w2, w2t, FF_, D_, D_,
                                                       (long)D_ * FF_, (long)D_ * FF_);
    transpose_f2h<<<dim3(D_ / 32, DK_ / 32, L_), tb>>>(wo, wot, DK_, D_, D_,
                                                       (long)DK_ * D_, (long)DK_ * D_);
    qkvpack<<<dim3(D_ / 256, NQKV, L_), 256>>>(wq, wk, wv, bq, bk, bv, wqkvt, bqkv);

    embed_kernel<<<BS_, 256>>>(seq, emb, pes, x, xh);

    for (int l = 0; l < L_; l++) {
        const __half* w1tl = w1t + (long)l * FF_ * D_;
        const __half* w2tl = w2t + (long)l * D_ * FF_;
        const __half* wotl = wot + (long)l * D_ * DK_;
        const __half* wqkvtl = wqkvt + (long)l * NQKV * D_;
        const float* bqkvl = bqkv + l * NQKV;

        // QKV: qkvh[4096, 0:192] = xh @ wqkvt^T + bqkv   (pitch 256)
        wgemm<64, 0><<<dim3(NQ_ / 64, BS_ / 128, 1), 256, SM_64>>>(
            xh, D_, wqkvtl, D_, bqkvl, nullptr, qkvh, NQ_, NQKV, D_, 0, 0, 0,
            0, nullptr, nullptr, nullptr, nullptr, nullptr);

        // scores (half out): sch[b,512,512] = 0.125 * q @ k^T
        wgemm<128, 0><<<dim3(S_ / 128, S_ / 128, B_), 256, SM_128>>>(
            qkvh, NQKV, qkvh + 64, NQKV, nullptr, nullptr, sch, S_, S_, DK_,
            (long)S_ * NQKV, (long)S_ * NQKV, (long)S_ * S_,
            3, nullptr, nullptr, nullptr, nullptr, nullptr);

        softmax_warp<<<B_ * S_ / 8, 256>>>(sch, ph);

        // head: hh[b,512,64] = ph @ v   (V row-major directly from qkvh[:,128:192])
        wgemm<64, 1><<<dim3(1, S_ / 128, B_), 256, SM_64>>>(
            ph, S_, qkvh + 128, NQKV, nullptr, nullptr, hh, DK_, DK_, S_,
            (long)S_ * S_, (long)S_ * NQKV, (long)S_ * DK_,
            0, nullptr, nullptr, nullptr, nullptr, nullptr);

        // att out + residual + BN: x = BN(x + hh @ wo + bo)
        wgemm<128, 0><<<dim3(D_ / 128, BS_ / 128, 1), 256, SM_128>>>(
            hh, DK_, wotl, DK_, bo + l * D_, x, xh, D_, D_, DK_, 0, 0, 0,
            2, x, agam + l * D_, abet + l * D_, amea + l * D_, avar + l * D_);

        // FFN1: fh = relu(xh @ w1 + b1)
        wgemm<128, 0><<<dim3(FF_ / 128, BS_ / 128, 1), 256, SM_128>>>(
            xh, D_, w1tl, D_, bff1 + l * FF_, nullptr, fh, FF_, FF_, D_, 0, 0, 0,
            1, nullptr, nullptr, nullptr, nullptr, nullptr);

        // FFN2 + residual + BN
        float* dst = (l == L_ - 1) ? out : x;
        wgemm<128, 0><<<dim3(D_ / 128, BS_ / 128, 1), 256, SM_128>>>(
            fh, FF_, w2tl, FF_, bff2 + l * D_, dst, xh, D_, D_, FF_, 0, 0, 0,
            2, x, fgam + l * D_, fbet + l * D_, fmea + l * D_, fvar + l * D_);
    }
}

// round 15
// speedup vs baseline: 1.1783x; 1.0006x over previous
#include <cuda_runtime.h>
#include <cuda_fp16.h>
#include <mma.h>
#include <math.h>
#include <stdint.h>

using namespace nvcuda;

// Problem dims
#define L_   4
#define D_   1024
#define DK_  64
#define B_   8
#define S_   512
#define FF_  4096
#define BS_  (B_ * S_)           // 4096 rows
#define NQKV 256                 // qkv buffer pitch (192 used: q|k|v)
#define NQ_  192                 // computed qkv columns
#define EPS_ 1e-3f

// -------------------- scratch (device globals; no allocations) ---------------
__device__ float  g_x[BS_ * D_];             // activations fp32 (residual source)
__device__ __half g_xh[BS_ * D_];            // activations half (GEMM A)
__device__ __half g_qkvh[BS_ * NQKV];        // q|k|v half (pitch 256)
__device__ __half g_sch[B_ * S_ * S_];       // scores half
__device__ __half g_ph[B_ * S_ * S_];        // probs half
__device__ __half g_hh[BS_ * DK_];           // head out half
__device__ __half g_fh[BS_ * FF_];           // ffn hidden half
__device__ __half g_w1t[L_ * FF_ * D_];      // w1^T half
__device__ __half g_w2t[L_ * D_ * FF_];      // w2^T half
__device__ __half g_wot[L_ * D_ * DK_];      // wo^T half
__device__ __half g_wqkvt[L_ * NQKV * D_];   // packed qkv^T half
__device__ float  g_bqkv[L_ * NQKV];

__device__ __forceinline__ uint32_t smem_u32(const void* p) {
    uint32_t a;
    asm("{ .reg .u64 t; cvta.to.shared.u64 t, %1; cvt.u32.u64 %0, t; }" : "=r"(a) : "l"(p));
    return a;
}

// ======================= wmma FP16 pipelined GEMM ============================
// C[M, N] = A[M, K(ldA)] @ B   (A, B half)
// BRM==0: B is Bt [N, K] K-major (ldB)   BRM==1: B is [K, N] row-major (ldB)
// CTA tile 128 x BN, K chunk 64, 3-stage cp.async pipeline, 8 warps (4m x 2n),
// warp tile 32 x (BN/2), wmma m16n16k16 fp16 -> fp32 accum.
// Outputs: Cf (fp32, optional) and Ch (half, optional), pitch ldC.
// mode 0: +bias   1: +bias, relu   2: BN(res + bias + acc)   3: acc * 0.125
#define STAGES 3

template<int BN, int BRM>
__global__ void __launch_bounds__(256, 2) wgemm(
    const __half* __restrict__ A, int ldA,
    const __half* __restrict__ B, int ldB,
    const float* __restrict__ bias,
    float* __restrict__ Cf, __half* __restrict__ Ch,
    int N, int ldC, int K, long sA, long sB, long sC,
    int mode,
    const float* __restrict__ res,
    const float* __restrict__ gamma, const float* __restrict__ beta,
    const float* __restrict__ mean,  const float* __restrict__ var)
{
    constexpr int BM = 128, BK = 64;
    constexpr int LDSA = BK + 8;                        // 72 halves (144B)
    constexpr int LDSB = BRM ? (BN + 8) : (BK + 8);
    constexpr int A_STG = BM * LDSA;                    // halves
    constexpr int B_STG = BRM ? (BK * LDSB) : (BN * LDSB);
    constexpr int STG = A_STG + B_STG;
    constexpr int WN = BN / 2;                          // warp n extent
    constexpr int NT = WN / 16;

    extern __shared__ char smraw[];
    __half* sm = (__half*)smraw;

    const int tid = threadIdx.x;
    const int wid = tid >> 5;
    const int warp_m = wid & 3;
    const int warp_n = wid >> 2;
    const int m0 = blockIdx.y * BM;
    const int n0 = blockIdx.x * BN;
    const int bz = blockIdx.z;
    A += bz * sA; B += bz * sB;
    if (Cf)  Cf += bz * sC;
    if (Ch)  Ch += bz * sC;
    if (res) res += bz * sC;

    const int NK = K >> 6;

    auto load_chunk = [&](int chunk, int stage) {
        __half* smA = sm + stage * STG;
        __half* smB = smA + A_STG;
        const __half* gA = A + (long)m0 * ldA + chunk * 64;
        #pragma unroll
        for (int j = 0; j < 4; j++) {                   // A: 128 rows x 8 x 16B
            int idx = tid + j * 256;
            int r = idx >> 3, c8 = (idx & 7) * 8;
            uint32_t dst = smem_u32(&smA[r * LDSA + c8]);
            const __half* src = gA + (long)r * ldA + c8;
            asm volatile("cp.async.cg.shared.global [%0], [%1], 16;" :: "r"(dst), "l"(src));
        }
        if (BRM) {
            const __half* gB = B + (long)(chunk * 64) * ldB + n0;
            constexpr int CPR = BN / 8;
            #pragma unroll
            for (int j = 0; j < BN / 32; j++) {         // 64 rows x CPR x 16B
                int idx = tid + j * 256;
                int r = idx / CPR, c8 = (idx % CPR) * 8;
                uint32_t dst = smem_u32(&smB[r * LDSB + c8]);
                const __half* src = gB + (long)r * ldB + c8;
                asm volatile("cp.async.cg.shared.global [%0], [%1], 16;" :: "r"(dst), "l"(src));
            }
        } else {
            const __half* gB = B + (long)n0 * ldB + chunk * 64;
            #pragma unroll
            for (int j = 0; j < BN / 32; j++) {         // BN rows x 8 x 16B
                int idx = tid + j * 256;
                int r = idx >> 3, c8 = (idx & 7) * 8;
                uint32_t dst = smem_u32(&smB[r * LDSB + c8]);
                const __half* src = gB + (long)r * ldB + c8;
                asm volatile("cp.async.cg.shared.global [%0], [%1], 16;" :: "r"(dst), "l"(src));
            }
        }
        asm volatile("cp.async.commit_group;" ::: "memory");
    };

    wmma::fragment<wmma::accumulator, 16, 16, 16, float> acc[2][NT];
    #pragma unroll
    for (int i = 0; i < 2; i++)
        #pragma unroll
        for (int j = 0; j < NT; j++) wmma::fill_fragment(acc[i][j], 0.f);

    load_chunk(0, 0);
    if (NK > 1) load_chunk(1, 1);

    for (int i = 0; i < NK; i++) {
        if (i < NK - 1) asm volatile("cp.async.wait_group 1;" ::: "memory");
        else            asm volatile("cp.async.wait_group 0;" ::: "memory");
        __syncthreads();

        if (i + 2 < NK) load_chunk(i + 2, (i + 2) % STAGES);

        const __half* sA = sm + (i % STAGES) * STG;
        const __half* sB = sA + A_STG;

        #pragma unroll
        for (int ks = 0; ks < 4; ks++) {
            int kk = ks * 16;
            wmma::fragment<wmma::matrix_a, 16, 16, 16, __half, wmma::row_major> af[2];
            #pragma unroll
            for (int mi = 0; mi < 2; mi++)
                wmma::load_matrix_sync(af[mi], sA + (warp_m * 32 + mi * 16) * LDSA + kk, LDSA);
            if (BRM) {
                wmma::fragment<wmma::matrix_b, 16, 16, 16, __half, wmma::row_major> bf[NT];
                #pragma unroll
                for (int nj = 0; nj < NT; nj++)
                    wmma::load_matrix_sync(bf[nj], sB + kk * LDSB + warp_n * WN + nj * 16, LDSB);
                #pragma unroll
                for (int mi = 0; mi < 2; mi++)
                    #pragma unroll
                    for (int nj = 0; nj < NT; nj++)
                        wmma::mma_sync(acc[mi][nj], af[mi], bf[nj], acc[mi][nj]);
            } else {
                wmma::fragment<wmma::matrix_b, 16, 16, 16, __half, wmma::col_major> bf[NT];
                #pragma unroll
                for (int nj = 0; nj < NT; nj++)
                    wmma::load_matrix_sync(bf[nj], sB + (warp_n * WN + nj * 16) * LDSB + kk, LDSB);
                #pragma unroll
                for (int mi = 0; mi < 2; mi++)
                    #pragma unroll
                    for (int nj = 0; nj < NT; nj++)
                        wmma::mma_sync(acc[mi][nj], af[mi], bf[nj], acc[mi][nj]);
            }
        }
    }
    __syncthreads();

    // ---------------- epilogue: fp32 staging in smem, fused ops --------------
    float* stg = (float*)smraw;
    #pragma unroll
    for (int mi = 0; mi < 2; mi++)
        #pragma unroll
        for (int nj = 0; nj < NT; nj++)
            wmma::store_matrix_sync(
                stg + (long)(warp_m * 32 + mi * 16) * BN + warp_n * WN + nj * 16,
                acc[mi][nj], BN, wmma::mem_row_major);
    __syncthreads();

    #pragma unroll
    for (int it = 0; it < BM * BN / 4 / 256; it++) {
        int idx = (tid + it * 256) * 4;
        int r = idx / BN, c = idx % BN;
        int gc = n0 + c;
        float4 o = *(const float4*)&stg[idx];
        if (bias) {
            float4 bb = *(const float4*)&bias[gc];
            o.x += bb.x; o.y += bb.y; o.z += bb.z; o.w += bb.w;
        }
        if (mode == 1) {
            o.x = fmaxf(o.x, 0.f); o.y = fmaxf(o.y, 0.f);
            o.z = fmaxf(o.z, 0.f); o.w = fmaxf(o.w, 0.f);
        } else if (mode == 2) {
            float4 rr = *(const float4*)&res[(long)(m0 + r) * ldC + gc];
            float4 gg = *(const float4*)&gamma[gc];
            float4 be = *(const float4*)&beta[gc];
            float4 mm = *(const float4*)&mean[gc];
            float4 va = *(const float4*)&var[gc];
            o.x = gg.x * (o.x + rr.x - mm.x) * rsqrtf(va.x + EPS_) + be.x;
            o.y = gg.y * (o.y + rr.y - mm.y) * rsqrtf(va.y + EPS_) + be.y;
            o.z = gg.z * (o.z + rr.z - mm.z) * rsqrtf(va.z + EPS_) + be.z;
            o.w = gg.w * (o.w + rr.w - mm.w) * rsqrtf(va.w + EPS_) + be.w;
        } else if (mode == 3) {
            o.x *= 0.125f; o.y *= 0.125f; o.z *= 0.125f; o.w *= 0.125f;
        }
        long off = (long)(m0 + r) * ldC + gc;
        if (Cf) *(float4*)&Cf[off] = o;
        if (Ch) {
            __half2 h0 = __floats2half2_rn(o.x, o.y);
            __half2 h1 = __floats2half2_rn(o.z, o.w);
            *(uint2*)&Ch[off] = make_uint2(*(uint32_t*)&h0, *(uint32_t*)&h1);
        }
    }
}

// ======================= small prep / misc kernels ===========================
__global__ void __launch_bounds__(256) embed_kernel(
    const int* __restrict__ seq, const float* __restrict__ emb,
    const float* __restrict__ pes, float* __restrict__ x, __half* __restrict__ xh)
{
    int bs = blockIdx.x;
    int s  = bs & (S_ - 1);
    int tok = seq[bs];
    float p = pes[(long)s * D_];
    const float4* e = (const float4*)(emb + (long)tok * D_);
    float4 v = e[threadIdx.x];
    v.x += p; v.y += p; v.z += p; v.w += p;
    ((float4*)(x + (long)bs * D_))[threadIdx.x] = v;
    __half2 h0 = __floats2half2_rn(v.x, v.y);
    __half2 h1 = __floats2half2_rn(v.z, v.w);
    ((uint2*)(xh + (long)bs * D_))[threadIdx.x] = make_uint2(*(uint32_t*)&h0, *(uint32_t*)&h1);
}

// fp32 -> half transpose: out[c][r] = in[r][c]; batched by blockIdx.z
__global__ void __launch_bounds__(256) transpose_f2h(
    const float* __restrict__ in, __half* __restrict__ out,
    int R, int C, int ldIn, long sIn, long sOut)
{
    __shared__ float t[32][33];
    in += (long)blockIdx.z * sIn; out += (long)blockIdx.z * sOut;
    int c0 = blockIdx.x * 32, r0 = blockIdx.y * 32;
    int tx = threadIdx.x, ty = threadIdx.y;
    #pragma unroll
    for (int j = 0; j < 32; j += 8)
        t[ty + j][tx] = in[(long)(r0 + ty + j) * ldIn + c0 + tx];
    __syncthreads();
    #pragma unroll
    for (int j = 0; j < 32; j += 8)
        out[(long)(c0 + ty + j) * R + r0 + tx] = __float2half_rn(t[tx][ty + j]);
}

// pack wq|wk|wv -> half wqkvt [L][256][1024] (transposed) + fp32 bias pack
__global__ void __launch_bounds__(256) qkvpack(
    const float* __restrict__ wq, const float* __restrict__ wk,
    const float* __restrict__ wv, const float* __restrict__ bq,
    const float* __restrict__ bk, const float* __restrict__ bv,
    __half* __restrict__ wt, float* __restrict__ bt)
{
    int l = blockIdx.z;
    int n = blockIdx.y;                         // 0..255
    int k = blockIdx.x * 256 + threadIdx.x;     // 0..1023
    const float* src = (n < 64) ? wq : (n < 128) ? wk : (n < 192) ? wv : nullptr;
    int j = n & 63;
    float v = 0.f;
    if (src) v = src[((long)l * D_ + k) * DK_ + j];
    wt[((long)l * NQKV + n) * D_ + k] = __float2half_rn(v);
    if (blockIdx.x == 0 && threadIdx.x == 0) {
        const float* bs = (n < 64) ? bq : (n < 128) ? bk : (n < 192) ? bv : nullptr;
        bt[l * NQKV + n] = bs ? bs[l * DK_ + j] : 0.f;
    }
}

// warp-per-row softmax over 512 half scores -> half probs (fp32 math)
__global__ void __launch_bounds__(256) softmax_warp(
    const __half* __restrict__ sc, __half* __restrict__ ph)
{
    int row = blockIdx.x * 8 + (threadIdx.x >> 5);
    int lane = threadIdx.x & 31;
    const __half2* r = (const __half2*)(sc + (long)row * S_);
    __half2* o = (__half2*)(ph + (long)row * S_);

    float v[16];
    float m = -1e30f;
    #pragma unroll
    for (int j = 0; j < 8; j++) {
        float2 f = __half22float2(r[lane + j * 32]);
        v[2 * j] = f.x; v[2 * j + 1] = f.y;
        m = fmaxf(m, fmaxf(f.x, f.y));
    }
    #pragma unroll
    for (int s = 16; s > 0; s >>= 1) m = fmaxf(m, __shfl_xor_sync(~0u, m, s));
    float sum = 0.f;
    #pragma unroll
    for (int j = 0; j < 16; j++) { v[j] = __expf(v[j] - m); sum += v[j]; }
    #pragma unroll
    for (int s = 16; s > 0; s >>= 1) sum += __shfl_xor_sync(~0u, sum, s);
    float inv = 1.0f / sum;
    #pragma unroll
    for (int j = 0; j < 8; j++)
        o[lane + j * 32] = __floats2half2_rn(v[2 * j] * inv, v[2 * j + 1] * inv);
}

// ------------------------------------------------------------------------------
extern "C" void kernel_launch(void* const* d_in, const int* in_sizes, int n_in,
                              void* d_out, int out_size)
{
    const int*   seq  = (const int*)  d_in[0];
    const float* emb  = (const float*)d_in[1];
    const float* pes  = (const float*)d_in[2];
    const float* wq   = (const float*)d_in[3];
    const float* bq   = (const float*)d_in[4];
    const float* wk   = (const float*)d_in[5];
    const float* bk   = (const float*)d_in[6];
    const float* wv   = (const float*)d_in[7];
    const float* bv   = (const float*)d_in[8];
    const float* wo   = (const float*)d_in[9];
    const float* bo   = (const float*)d_in[10];
    const float* agam = (const float*)d_in[11];
    const float* abet = (const float*)d_in[12];
    const float* amea = (const float*)d_in[13];
    const float* avar = (const float*)d_in[14];
    const float* w1   = (const float*)d_in[15];
    const float* bff1 = (const float*)d_in[16];
    const float* w2   = (const float*)d_in[17];
    const float* bff2 = (const float*)d_in[18];
    const float* fgam = (const float*)d_in[19];
    const float* fbet = (const float*)d_in[20];
    const float* fmea = (const float*)d_in[21];
    const float* fvar = (const float*)d_in[22];
    float* out = (float*)d_out;

    float *x, *bqkv;
    __half *xh, *qkvh, *sch, *ph, *hh, *fh, *w1t, *w2t, *wot, *wqkvt;
    cudaGetSymbolAddress((void**)&x, g_x);
    cudaGetSymbolAddress((void**)&xh, g_xh);
    cudaGetSymbolAddress((void**)&qkvh, g_qkvh);
    cudaGetSymbolAddress((void**)&sch, g_sch);
    cudaGetSymbolAddress((void**)&ph, g_ph);
    cudaGetSymbolAddress((void**)&hh, g_hh);
    cudaGetSymbolAddress((void**)&fh, g_fh);
    cudaGetSymbolAddress((void**)&w1t, g_w1t);
    cudaGetSymbolAddress((void**)&w2t, g_w2t);
    cudaGetSymbolAddress((void**)&wot, g_wot);
    cudaGetSymbolAddress((void**)&wqkvt, g_wqkvt);
    cudaGetSymbolAddress((void**)&bqkv, g_bqkv);

    // lazy one-time stream/event setup (resource init only; no work is skipped)
    static cudaStream_t s_prep = nullptr;
    static cudaEvent_t e_fork, e_qkv, e_wo, e_w1, e_w2;
    if (!s_prep) {
        cudaStreamCreateWithFlags(&s_prep, cudaStreamNonBlocking);
        cudaEventCreateWithFlags(&e_fork, cudaEventDisableTiming);
        cudaEventCreateWithFlags(&e_qkv,  cudaEventDisableTiming);
        cudaEventCreateWithFlags(&e_wo,   cudaEventDisableTiming);
        cudaEventCreateWithFlags(&e_w1,   cudaEventDisableTiming);
        cudaEventCreateWithFlags(&e_w2,   cudaEventDisableTiming);
    }

    // dynamic smem: 3 stages * (A + B) halves * 2B  (epilogue staging fits within)
    const int SM_64  = 3 * (128 * 72 + 64 * 72) * 2;    // 82944
    const int SM_128 = 3 * (128 * 72 + 128 * 72) * 2;   // 110592
    cudaFuncSetAttribute((const void*)wgemm<64, 0>,
                         cudaFuncAttributeMaxDynamicSharedMemorySize, SM_64);
    cudaFuncSetAttribute((const void*)wgemm<64, 1>,
                         cudaFuncAttributeMaxDynamicSharedMemorySize, SM_64);
    cudaFuncSetAttribute((const void*)wgemm<128, 0>,
                         cudaFuncAttributeMaxDynamicSharedMemorySize, SM_128);

    dim3 tb(32, 8);

    // ---- fork: weight prep on s_prep, ordered by first use in layer 0 -------
    cudaEventRecord(e_fork, 0);
    cudaStreamWaitEvent(s_prep, e_fork, 0);

    qkvpack<<<dim3(D_ / 256, NQKV, L_), 256, 0, s_prep>>>(
        wq, wk, wv, bq, bk, bv, wqkvt, bqkv);
    cudaEventRecord(e_qkv, s_prep);

    transpose_f2h<<<dim3(D_ / 32, DK_ / 32, L_), tb, 0, s_prep>>>(
        wo, wot, DK_, D_, D_, (long)DK_ * D_, (long)DK_ * D_);
    cudaEventRecord(e_wo, s_prep);

    transpose_f2h<<<dim3(FF_ / 32, D_ / 32, L_), tb, 0, s_prep>>>(
        w1, w1t, D_, FF_, FF_, (long)D_ * FF_, (long)D_ * FF_);
    cudaEventRecord(e_w1, s_prep);

    transpose_f2h<<<dim3(D_ / 32, FF_ / 32, L_), tb, 0, s_prep>>>(
        w2, w2t, FF_, D_, D_, (long)D_ * FF_, (long)D_ * FF_);
    cudaEventRecord(e_w2, s_prep);

    // ---- main stream: embed immediately, then layers ------------------------
    embed_kernel<<<BS_, 256>>>(seq, emb, pes, x, xh);

    for (int l = 0; l < L_; l++) {
        const __half* w1tl = w1t + (long)l * FF_ * D_;
        const __half* w2tl = w2t + (long)l * D_ * FF_;
        const __half* wotl = wot + (long)l * D_ * DK_;
        const __half* wqkvtl = wqkvt + (long)l * NQKV * D_;
        const float* bqkvl = bqkv + l * NQKV;

        // QKV: qkvh[4096, 0:192] = xh @ wqkvt^T + bqkv   (pitch 256)
        if (l == 0) cudaStreamWaitEvent(0, e_qkv, 0);
        wgemm<64, 0><<<dim3(NQ_ / 64, BS_ / 128, 1), 256, SM_64>>>(
            xh, D_, wqkvtl, D_, bqkvl, nullptr, qkvh, NQ_, NQKV, D_, 0, 0, 0,
            0, nullptr, nullptr, nullptr, nullptr, nullptr);

        // scores (half out): sch[b,512,512] = 0.125 * q @ k^T
        wgemm<128, 0><<<dim3(S_ / 128, S_ / 128, B_), 256, SM_128>>>(
            qkvh, NQKV, qkvh + 64, NQKV, nullptr, nullptr, sch, S_, S_, DK_,
            (long)S_ * NQKV, (long)S_ * NQKV, (long)S_ * S_,
            3, nullptr, nullptr, nullptr, nullptr, nullptr);

        softmax_warp<<<B_ * S_ / 8, 256>>>(sch, ph);

        // head: hh[b,512,64] = ph @ v   (V row-major directly from qkvh[:,128:192])
        wgemm<64, 1><<<dim3(1, S_ / 128, B_), 256, SM_64>>>(
            ph, S_, qkvh + 128, NQKV, nullptr, nullptr, hh, DK_, DK_, S_,
            (long)S_ * S_, (long)S_ * NQKV, (long)S_ * DK_,
            0, nullptr, nullptr, nullptr, nullptr, nullptr);

        // att out + residual + BN: x = BN(x + hh @ wo + bo)
        if (l == 0) cudaStreamWaitEvent(0, e_wo, 0);
        wgemm<128, 0><<<dim3(D_ / 128, BS_ / 128, 1), 256, SM_128>>>(
            hh, DK_, wotl, DK_, bo + l * D_, x, xh, D_, D_, DK_, 0, 0, 0,
            2, x, agam + l * D_, abet + l * D_, amea + l * D_, avar + l * D_);

        // FFN1: fh = relu(xh @ w1 + b1)
        if (l == 0) cudaStreamWaitEvent(0, e_w1, 0);
        wgemm<128, 0><<<dim3(FF_ / 128, BS_ / 128, 1), 256, SM_128>>>(
            xh, D_, w1tl, D_, bff1 + l * FF_, nullptr, fh, FF_, FF_, D_, 0, 0, 0,
            1, nullptr, nullptr, nullptr, nullptr, nullptr);

        // FFN2 + residual + BN
        if (l == 0) cudaStreamWaitEvent(0, e_w2, 0);
        float* dst = (l == L_ - 1) ? out : x;
        wgemm<128, 0><<<dim3(D_ / 128, BS_ / 128, 1), 256, SM_128>>>(
            fh, FF_, w2tl, FF_, bff2 + l * D_, dst, xh, D_, D_, FF_, 0, 0, 0,
            2, x, fgam + l * D_, fbet + l * D_, fmea + l * D_, fvar + l * D_);
    }
}